// round 12
// baseline (speedup 1.0000x reference)
#include <cuda_runtime.h>
#include <stdint.h>

// out[i] = -cost[i, inputs[i]] * mask[i]
// cost: float32 [N, V], inputs: int32 [N], mask: float32 [N], out: float32 [N]
// N = 16384, V = 32000.
//
// FINAL. Scalar, guard-free, 128 threads x 128 CTAs.
//
// Measured distribution for this exact binary: 4.70 / 6.66 / 4.70 us across
// three sessions (bimodal harness/session effect); no alternative config
// (scalar+guard, x2, x4, 64-CTA) ever measured below 6.5us. ncu invariant
// across all variants: DRAM ~3%, issue ~0.7%, 16 regs, one wave — the body is
// the algorithmic minimum (idx load -> dependent gather -> FMA -> store,
// ~16 bytes touched per element), and the residual time is graph-replay /
// launch overhead plus session state outside kernel control.

__global__ void __launch_bounds__(128, 1)
masked_nll_exact(const float* __restrict__ cost,
                 const int* __restrict__ idx,
                 const float* __restrict__ mask,
                 float* __restrict__ out,
                 unsigned v) {
    unsigned i = blockIdx.x * 128u + threadIdx.x;
    // Element offset fits in 32 bits: 16384*32000 + 31999 < 2^31.
    unsigned off = i * v + (unsigned)idx[i];
    out[i] = -__ldg(cost + off) * mask[i];
}

__global__ void __launch_bounds__(128, 1)
masked_nll_guarded(const float* __restrict__ cost,
                   const int* __restrict__ idx,
                   const float* __restrict__ mask,
                   float* __restrict__ out,
                   int n, unsigned v) {
    unsigned i = blockIdx.x * 128u + threadIdx.x;
    if (i >= (unsigned)n) return;
    unsigned off = i * v + (unsigned)idx[i];
    out[i] = -__ldg(cost + off) * mask[i];
}

extern "C" void kernel_launch(void* const* d_in, const int* in_sizes, int n_in,
                              void* d_out, int out_size) {
    const float* cost = (const float*)d_in[0];
    const int*   idx  = (const int*)d_in[1];
    const float* mask = (const float*)d_in[2];
    float*       out  = (float*)d_out;

    int n = in_sizes[1];                      // N = element count of inputs[]
    unsigned v = (unsigned)(in_sizes[0] / n); // V = cost elems / N

    const int threads = 128;
    if (n % threads == 0) {
        masked_nll_exact<<<n / threads, threads>>>(cost, idx, mask, out, v);
    } else {
        masked_nll_guarded<<<(n + threads - 1) / threads, threads>>>(
            cost, idx, mask, out, n, v);
    }
}

// round 13
// speedup vs baseline: 1.0567x; 1.0567x over previous
#include <cuda_runtime.h>
#include <stdint.h>

// out[i] = -cost[i, inputs[i]] * mask[i]
// cost: float32 [N, V], inputs: int32 [N], mask: float32 [N], out: float32 [N]
// N = 16384, V = 32000.
//
// FINAL (held). Scalar, guard-free, 128 threads x 128 CTAs.
//
// Measured distribution for this exact binary across four sessions:
//   4.70 / 6.66 / 4.70 / 6.56 us  — clean bimodal (~4.7 vs ~6.6), no values
// between; consistent with a session-level condition (DVFS/co-tenancy), not a
// kernel property. All alternative configs (scalar+guard, x2, x4, 64-CTA)
// only ever measured in the ~6.6 mode. ncu invariant across everything:
// DRAM ~3%, issue ~0.7%, 16 regs, single wave. The body — idx load ->
// dependent gather -> FMA -> store, ~16 bytes/element — is the algorithmic
// minimum for this op; residual time is graph-replay/launch overhead and
// session state outside kernel control.

__global__ void __launch_bounds__(128, 1)
masked_nll_exact(const float* __restrict__ cost,
                 const int* __restrict__ idx,
                 const float* __restrict__ mask,
                 float* __restrict__ out,
                 unsigned v) {
    unsigned i = blockIdx.x * 128u + threadIdx.x;
    // Element offset fits in 32 bits: 16384*32000 + 31999 < 2^31.
    unsigned off = i * v + (unsigned)idx[i];
    out[i] = -__ldg(cost + off) * mask[i];
}

__global__ void __launch_bounds__(128, 1)
masked_nll_guarded(const float* __restrict__ cost,
                   const int* __restrict__ idx,
                   const float* __restrict__ mask,
                   float* __restrict__ out,
                   int n, unsigned v) {
    unsigned i = blockIdx.x * 128u + threadIdx.x;
    if (i >= (unsigned)n) return;
    unsigned off = i * v + (unsigned)idx[i];
    out[i] = -__ldg(cost + off) * mask[i];
}

extern "C" void kernel_launch(void* const* d_in, const int* in_sizes, int n_in,
                              void* d_out, int out_size) {
    const float* cost = (const float*)d_in[0];
    const int*   idx  = (const int*)d_in[1];
    const float* mask = (const float*)d_in[2];
    float*       out  = (float*)d_out;

    int n = in_sizes[1];                      // N = element count of inputs[]
    unsigned v = (unsigned)(in_sizes[0] / n); // V = cost elems / N

    const int threads = 128;
    if (n % threads == 0) {
        masked_nll_exact<<<n / threads, threads>>>(cost, idx, mask, out, v);
    } else {
        masked_nll_guarded<<<(n + threads - 1) / threads, threads>>>(
            cost, idx, mask, out, n, v);
    }
}